// round 8
// baseline (speedup 1.0000x reference)
#include <cuda_runtime.h>
#include <cuda_bf16.h>
#include <cstdint>

// Problem constants
#define NN 8
#define AA 256
#define HH 128
#define WW 128
#define CC 19
#define CP1 20
#define HT 1024
#define WT 1024
#define RPB 16             // h-rows per stats block
#define ACOLS 64           // a-columns per stats block
#define SEGW 22            // ushorts per window segment record (1 cnt + <=20 segs + pad)

// Device scratch (no cudaMalloc allowed)
__device__ float gSums[CP1 * AA];
__device__ float gSq[CP1 * AA];
__device__ float gCount[32];
__device__ float gS[CP1 * CC];
__device__ unsigned char gLab[NN * HH * WW];
__device__ unsigned char gSW[NN * HH * WW];          // per-row sorted pixel w (uchar)
__device__ unsigned short gSegs[NN * HH * 4 * SEGW]; // per-row per-32-window segments
__device__ int gIs64;

// ---------------------------------------------------------------------------
// K0a: detect target dtype (int32 vs int64). int64 labels in [0,19): every
// odd 32-bit word is a zero high-word. Reads first 8192 words only (safe).
// ---------------------------------------------------------------------------
__global__ void detect_kernel(const int* __restrict__ tw) {
    __shared__ int anynz;
    if (threadIdx.x == 0) anynz = 0;
    __syncthreads();
    int v = 0;
    #pragma unroll
    for (int k = 0; k < 16; k++) {
        int idx = threadIdx.x * 16 + k;          // 0..4095
        v |= tw[idx * 2 + 1];                    // word idx <= 8191
    }
    if (v != 0) atomicOr(&anynz, 1);
    __syncthreads();
    if (threadIdx.x == 0) gIs64 = (anynz == 0) ? 1 : 0;
}

// ---------------------------------------------------------------------------
// K0b: zero the per-class accumulators
// ---------------------------------------------------------------------------
__global__ void zero_kernel() {
    int i = blockIdx.x * 256 + threadIdx.x;
    if (i < CP1 * AA) { gSums[i] = 0.f; gSq[i] = 0.f; }
    if (i < 32) gCount[i] = 0.f;
}

// ---------------------------------------------------------------------------
// K0c: per-row label fetch + counting sort + per-window segment extraction.
// One block per (n,h) row. Writes gSW (sorted pixel order, uchar), gSegs
// (per-32-pixel-window (class<<8|count) descriptors; classes are monotone in
// sorted order so <=20 segments per window), gLab (raw bytes), gCount.
// ---------------------------------------------------------------------------
__global__ void sort_kernel(const int* __restrict__ tw) {
    __shared__ int cnt[CP1];
    __shared__ int offs[CP1];
    __shared__ unsigned char slab[128];
    const int t = threadIdx.x;          // 0..127 (w)
    const int row = blockIdx.x;         // n*HH + h
    const int n = row >> 7;
    const int h = row & 127;

    long long eidx = ((long long)n * HT + (long long)h * 8) * WT + (long long)t * 8;
    int raw = gIs64 ? tw[eidx * 2] : tw[eidx];
    int l0 = (raw == 255) ? 0 : raw;
    if (l0 < 0) l0 = 0;
    if (l0 > CP1 - 1) l0 = CP1 - 1;

    if (t < CP1) cnt[t] = 0;
    __syncthreads();
    atomicAdd(&cnt[l0], 1);
    gLab[(size_t)row * WW + t] = (unsigned char)(raw & 0xFF);
    __syncthreads();
    if (t == 0) {
        int run = 0;
        #pragma unroll
        for (int c = 0; c < CP1; c++) { offs[c] = run; run += cnt[c]; }
    }
    if (t < CP1) atomicAdd(&gCount[t], (float)cnt[t]);
    __syncthreads();
    int pos = atomicAdd(&offs[l0], 1);
    slab[pos] = (unsigned char)l0;
    gSW[(size_t)row * WW + pos] = (unsigned char)t;
    __syncthreads();

    // per-32-window segment extraction (threads 0..3, serial scan of 32)
    if (t < 4) {
        unsigned short* out = gSegs + ((size_t)row * 4 + t) * SEGW;
        int base = t * 32;
        int run = slab[base];
        int c0 = 1, ns = 0;
        #pragma unroll 1
        for (int i = 1; i < 32; i++) {
            int c = slab[base + i];
            if (c == run) { c0++; }
            else {
                out[1 + ns] = (unsigned short)((run << 8) | c0);
                ns++; run = c; c0 = 1;
            }
        }
        out[1 + ns] = (unsigned short)((run << 8) | c0);
        ns++;
        out[0] = (unsigned short)ns;
    }
}

// ---------------------------------------------------------------------------
// K1: stats. Block = (a-quarter of 64, h-block of 16 rows, n) -> 256 blocks.
// 256 threads, ~110KB dynamic smem -> 2 CTA/SM.
// Staging: double-buffered 64a x 128w tile, pf[32] register prefetch for the
// next row issued before the sync (DRAM latency covered by accum + next STS).
// Accum: 4 groups of 2 warps; per group, two nested UNIFORM loops over the
// precomputed segment descriptors (no data-dependent ifs -> no BSSY/BSYNC,
// no predicated flush bodies). Running register accumulators flushed once
// per segment. One coalesced atomic flush per block at the end.
// ---------------------------------------------------------------------------
__global__ __launch_bounds__(256, 2)
void stats_kernel(const float* __restrict__ features) {
    extern __shared__ float sm[];
    float* buf  = sm;                              // [2][ACOLS*129]
    float* accS = sm + 2 * ACOLS * 129;            // [4][CP1][ACOLS]
    float* accQ = accS + 4 * CP1 * ACOLS;          // [4][CP1][ACOLS]
    unsigned short* segsm = (unsigned short*)(accQ + 4 * CP1 * ACOLS); // [RPB*4*SEGW]
    unsigned char*  swsm  = (unsigned char*)(segsm + RPB * 4 * SEGW);  // [RPB*128]

    const int t   = threadIdx.x;        // 0..255
    const int g   = t >> 6;             // pixel group 0..3
    const int tl  = t & 63;             // owned a-column within quarter
    const int w32 = t & 31;             // staging lane (w)
    const int rg  = t >> 5;             // staging row group 0..7
    const int q   = blockIdx.x;         // a-quarter 0..3
    const int hb  = blockIdx.y;         // 0..7
    const int n   = blockIdx.z;
    const int aBase = q * ACOLS;

    // zero accumulators + preload sort metadata for the 16 rows
    #pragma unroll
    for (int i = t; i < 4 * CP1 * ACOLS; i += 256) { accS[i] = 0.f; accQ[i] = 0.f; }
    {
        const int swbase = (n * HH + hb * RPB) * 128;
        #pragma unroll
        for (int i = t; i < RPB * 128; i += 256) swsm[i] = gSW[swbase + i];
        const int sgbase = (n * HH + hb * RPB) * 4 * SEGW;
        #pragma unroll
        for (int i = t; i < RPB * 4 * SEGW; i += 256) segsm[i] = gSegs[sgbase + i];
    }

    const float* fbase = features + ((size_t)(n * AA + aBase)) * (HH * WW)
                       + (size_t)(hb * RPB) * WW;

    // prologue: load row 0 into registers (8 a-rows x 4 w-chunks per thread)
    float pf[32];
    #pragma unroll
    for (int k = 0; k < 8; k++)
        #pragma unroll
        for (int m = 0; m < 4; m++)
            pf[k * 4 + m] = fbase[(size_t)(rg + 8 * k) * (HH * WW) + w32 + 32 * m];

    __syncthreads();   // metadata + acc zero visible

    #pragma unroll 1
    for (int ch = 0; ch < RPB; ch++) {
        float* bufc = buf + (ch & 1) * (ACOLS * 129);

        // store current row tile to its stage (conflict-free stride 129)
        #pragma unroll
        for (int k = 0; k < 8; k++)
            #pragma unroll
            for (int m = 0; m < 4; m++)
                bufc[(rg + 8 * k) * 129 + w32 + 32 * m] = pf[k * 4 + m];

        // issue next row's loads now; consumed at iteration ch+1's STS
        if (ch + 1 < RPB) {
            #pragma unroll
            for (int k = 0; k < 8; k++)
                #pragma unroll
                for (int m = 0; m < 4; m++)
                    pf[k * 4 + m] = fbase[(size_t)(rg + 8 * k) * (HH * WW)
                                          + (ch + 1) * WW + w32 + 32 * m];
        }
        __syncthreads();   // stage filled; orders accum(ch-1) vs STS(ch+1)

        // segment-loop accumulation: group g -> sorted pixels [32g, 32g+32)
        {
            const unsigned char*  swr = swsm + ch * 128 + g * 32;
            const unsigned short* sgr = segsm + (ch * 4 + g) * SEGW;
            const int nseg = sgr[0];
            int idx = 0;
            float* aS = accS + g * CP1 * ACOLS + tl;
            float* aQ = accQ + g * CP1 * ACOLS + tl;
            #pragma unroll 1
            for (int si = 1; si <= nseg; si++) {
                int sc  = sgr[si];                 // uniform LDS
                int cnt = sc & 255;
                int cls = sc >> 8;
                float s = 0.f, qq = 0.f;
                #pragma unroll 1
                for (int j = 0; j < cnt; j++) {    // uniform trip count
                    float f = bufc[tl * 129 + swr[idx + j]];
                    s  += f;
                    qq += f * f;
                }
                idx += cnt;
                aS[cls * ACOLS] += s;              // unconditional flush
                aQ[cls * ACOLS] += qq;
            }
        }
    }
    __syncthreads();

    // merge 4 groups, single coalesced atomic flush
    #pragma unroll
    for (int i = t; i < CP1 * ACOLS; i += 256) {
        int c = i >> 6, al = i & 63;
        float vs = 0.f, vq = 0.f;
        #pragma unroll
        for (int gg = 0; gg < 4; gg++) {
            vs += accS[(gg * CP1 + c) * ACOLS + al];
            vq += accQ[(gg * CP1 + c) * ACOLS + al];
        }
        atomicAdd(&gSums[c * AA + aBase + al], vs);
        atomicAdd(&gSq[c * AA + aBase + al],   vq);
    }
}

// ---------------------------------------------------------------------------
// K2: grid = 19 blocks (one per class l; ncov row 19 never read: lab0<=18).
// fc staged in smem; c-loop fully unrolled -> 19 independent shuffle chains.
// ---------------------------------------------------------------------------
__global__ __launch_bounds__(256)
void cov_s_kernel(const float* __restrict__ fc,
                  const float* __restrict__ Ave,
                  const float* __restrict__ CoV,
                  const float* __restrict__ Amount,
                  const int* __restrict__ ratio_p) {
    __shared__ float Wsm[CC * AA];
    __shared__ float red[CC][8];
    const int l = blockIdx.x;          // 0..18
    const int t = threadIdx.x;         // 0..255 == feature index a
    const int lane = t & 31, wid = t >> 5;

    #pragma unroll
    for (int c = 0; c < CC; c++) Wsm[c * AA + t] = fc[c * AA + t];

    float cntv = gCount[l];
    float sums = gSums[l * AA + t];
    float sq   = gSq[l * AA + t];
    float avev = Ave[l * AA + t];
    float covv = CoV[l * AA + t];
    float amov = Amount[l];
    float r    = (float)(*ratio_p);    // low 4 LE bytes: correct for i32 & i64

    float cntc = (cntv == 0.f) ? 1.f : cntv;
    float ave  = sums / cntc;
    float var  = sq / cntc - ave * ave;
    float denom = cntv + amov;
    float wcv  = (denom > 0.f) ? (cntv / denom) : 0.f;
    float dd   = avev - ave;
    float ncov = covv * (1.f - wcv) + var * wcv + wcv * (1.f - wcv) * dd * dd;

    __syncthreads();
    float wl = Wsm[l * AA + t];

    #pragma unroll
    for (int c = 0; c < CC; c++) {
        float d = Wsm[c * AA + t] - wl;
        float v = ncov * d * d;
        #pragma unroll
        for (int o = 16; o; o >>= 1) v += __shfl_down_sync(0xffffffffu, v, o);
        if (lane == 0) red[c][wid] = v;
    }
    __syncthreads();
    if (t < CC) {
        float s = 0.f;
        #pragma unroll
        for (int k = 0; k < 8; k++) s += red[t][k];
        gS[l * CC + t] = r * s;
    }
}

// ---------------------------------------------------------------------------
// K3: out[n,c,h,w] = y[n,c,h,w] + 0.5 * S[l(n,h,w), c] * (l != 255)
// 4 blocks per (n,c) -> 608 blocks, 256 threads, float4/uchar4
// ---------------------------------------------------------------------------
__global__ __launch_bounds__(256, 4)
void aug_kernel(const float* __restrict__ y, float* __restrict__ out) {
    __shared__ float Ssm[CP1];
    const int t = threadIdx.x;                 // 0..255
    const int bq = blockIdx.x & 3;             // h-quarter
    const int nc = blockIdx.x >> 2;
    const int n = nc / CC;
    const int c = nc % CC;

    if (t < CP1) Ssm[t] = (t < CC) ? (0.5f * gS[t * CC + c]) : 0.f;
    __syncthreads();

    const size_t plane = ((size_t)n * CC + c) * (HH * WW);
    const int qoff = bq * (HH * WW / 16);      // in float4 units
    const float4* y4 = (const float4*)(y + plane) + qoff;
    float4*       o4 = (float4*)(out + plane) + qoff;
    const uchar4* l4 = (const uchar4*)(gLab + (size_t)n * (HH * WW)) + qoff;

    #pragma unroll 4
    for (int i = t; i < (HH * WW) / 16; i += 256) {
        uchar4 lb = l4[i];
        float4 v  = y4[i];
        if (lb.x != 255) v.x += Ssm[lb.x];
        if (lb.y != 255) v.y += Ssm[lb.y];
        if (lb.z != 255) v.z += Ssm[lb.z];
        if (lb.w != 255) v.w += Ssm[lb.w];
        o4[i] = v;
    }
}

// ---------------------------------------------------------------------------
extern "C" void kernel_launch(void* const* d_in, const int* in_sizes, int n_in,
                              void* d_out, int out_size) {
    const float* features = (const float*)d_in[0];
    const float* y        = (const float*)d_in[1];
    const float* fc       = (const float*)d_in[2];
    const float* Ave      = (const float*)d_in[3];
    const float* CoV      = (const float*)d_in[4];
    const float* Amount   = (const float*)d_in[5];
    const int*   target_w = (const int*)d_in[6];   // int32 or int64 (probed)
    const int*   ratio    = (const int*)d_in[7];
    float*       out      = (float*)d_out;

    // launch idx 0: dtype probe
    detect_kernel<<<1, 256>>>(target_w);
    // launch idx 1: zero accumulators
    zero_kernel<<<(CP1 * AA + 255) / 256, 256>>>();
    // launch idx 2: per-row label sort + segment extraction
    sort_kernel<<<NN * HH, 128>>>(target_w);

    // launch idx 3 (the ncu-captured slot): stats
    const int smem1 = (2 * ACOLS * 129 + 8 * CP1 * ACOLS) * 4
                    + RPB * 4 * SEGW * 2 + RPB * 128;
    cudaFuncSetAttribute(stats_kernel, cudaFuncAttributeMaxDynamicSharedMemorySize, smem1);
    dim3 g1(4, HH / RPB, NN);
    stats_kernel<<<g1, 256, smem1>>>(features);

    // launch idx 4: covariance update + S table
    cov_s_kernel<<<CC, 256>>>(fc, Ave, CoV, Amount, ratio);

    // launch idx 5: output
    aug_kernel<<<NN * CC * 4, 256>>>(y, out);
}

// round 9
// speedup vs baseline: 1.0065x; 1.0065x over previous
#include <cuda_runtime.h>
#include <cuda_bf16.h>
#include <cstdint>

// Problem constants
#define NN 8
#define AA 256
#define HH 128
#define WW 128
#define CC 19
#define CP1 20
#define HT 1024
#define WT 1024
#define RPB 16             // h-rows per stats block
#define ACOLS 64           // a-columns per stats block
#define SEGW 22            // ushorts per window segment record (1 cnt + <=20 segs + pad)

// Device scratch (no cudaMalloc allowed)
__device__ float gSums[CP1 * AA];
__device__ float gSq[CP1 * AA];
__device__ float gCount[32];
__device__ float gS[CP1 * CC];
__device__ unsigned char gLab[NN * HH * WW];
__device__ unsigned char gSW[NN * HH * WW];          // per-row sorted pixel w (uchar)
__device__ unsigned short gSegs[NN * HH * 4 * SEGW]; // per-row per-32-window segments
__device__ int gIs64;

// ---------------------------------------------------------------------------
// K0a: detect target dtype (int32 vs int64). int64 labels in [0,19): every
// odd 32-bit word is a zero high-word. Reads first 8192 words only (safe).
// ---------------------------------------------------------------------------
__global__ void detect_kernel(const int* __restrict__ tw) {
    __shared__ int anynz;
    if (threadIdx.x == 0) anynz = 0;
    __syncthreads();
    int v = 0;
    #pragma unroll
    for (int k = 0; k < 16; k++) {
        int idx = threadIdx.x * 16 + k;          // 0..4095
        v |= tw[idx * 2 + 1];                    // word idx <= 8191
    }
    if (v != 0) atomicOr(&anynz, 1);
    __syncthreads();
    if (threadIdx.x == 0) gIs64 = (anynz == 0) ? 1 : 0;
}

// ---------------------------------------------------------------------------
// K0b: zero the per-class accumulators
// ---------------------------------------------------------------------------
__global__ void zero_kernel() {
    int i = blockIdx.x * 256 + threadIdx.x;
    if (i < CP1 * AA) { gSums[i] = 0.f; gSq[i] = 0.f; }
    if (i < 32) gCount[i] = 0.f;
}

// ---------------------------------------------------------------------------
// K0c: per-row label fetch + counting sort + per-window segment extraction.
// One block per (n,h) row. Writes gSW (sorted pixel order, uchar), gSegs
// (per-32-pixel-window (class<<8|count) descriptors; classes are monotone in
// sorted order so <=20 segments per window), gLab (raw bytes), gCount.
// ---------------------------------------------------------------------------
__global__ void sort_kernel(const int* __restrict__ tw) {
    __shared__ int cnt[CP1];
    __shared__ int offs[CP1];
    __shared__ unsigned char slab[128];
    const int t = threadIdx.x;          // 0..127 (w)
    const int row = blockIdx.x;         // n*HH + h
    const int n = row >> 7;
    const int h = row & 127;

    long long eidx = ((long long)n * HT + (long long)h * 8) * WT + (long long)t * 8;
    int raw = gIs64 ? tw[eidx * 2] : tw[eidx];
    int l0 = (raw == 255) ? 0 : raw;
    if (l0 < 0) l0 = 0;
    if (l0 > CP1 - 1) l0 = CP1 - 1;

    if (t < CP1) cnt[t] = 0;
    __syncthreads();
    atomicAdd(&cnt[l0], 1);
    gLab[(size_t)row * WW + t] = (unsigned char)(raw & 0xFF);
    __syncthreads();
    if (t == 0) {
        int run = 0;
        #pragma unroll
        for (int c = 0; c < CP1; c++) { offs[c] = run; run += cnt[c]; }
    }
    if (t < CP1) atomicAdd(&gCount[t], (float)cnt[t]);
    __syncthreads();
    int pos = atomicAdd(&offs[l0], 1);
    slab[pos] = (unsigned char)l0;
    gSW[(size_t)row * WW + pos] = (unsigned char)t;
    __syncthreads();

    // per-32-window segment extraction (threads 0..3, serial scan of 32)
    if (t < 4) {
        unsigned short* out = gSegs + ((size_t)row * 4 + t) * SEGW;
        int base = t * 32;
        int run = slab[base];
        int c0 = 1, ns = 0;
        #pragma unroll 1
        for (int i = 1; i < 32; i++) {
            int c = slab[base + i];
            if (c == run) { c0++; }
            else {
                out[1 + ns] = (unsigned short)((run << 8) | c0);
                ns++; run = c; c0 = 1;
            }
        }
        out[1 + ns] = (unsigned short)((run << 8) | c0);
        ns++;
        out[0] = (unsigned short)ns;
    }
}

// ---------------------------------------------------------------------------
// K1: stats. Block = (a-quarter of 64, h-block of 16 rows, n) -> 256 blocks.
// 256 threads, ~110KB dynamic smem -> 2 CTA/SM.
// Staging: double-buffered 64a x 128w tile, pf[32] register prefetch for the
// next row issued before the sync (DRAM latency covered by accum + next STS).
// Accum: 4 groups of 2 warps; per group, two nested UNIFORM loops over the
// precomputed segment descriptors (no data-dependent ifs -> no BSSY/BSYNC,
// no predicated flush bodies). Running register accumulators flushed once
// per segment. One coalesced atomic flush per block at the end.
// ---------------------------------------------------------------------------
__global__ __launch_bounds__(256, 2)
void stats_kernel(const float* __restrict__ features) {
    extern __shared__ float sm[];
    float* buf  = sm;                              // [2][ACOLS*129]
    float* accS = sm + 2 * ACOLS * 129;            // [4][CP1][ACOLS]
    float* accQ = accS + 4 * CP1 * ACOLS;          // [4][CP1][ACOLS]
    unsigned short* segsm = (unsigned short*)(accQ + 4 * CP1 * ACOLS); // [RPB*4*SEGW]
    unsigned char*  swsm  = (unsigned char*)(segsm + RPB * 4 * SEGW);  // [RPB*128]

    const int t   = threadIdx.x;        // 0..255
    const int g   = t >> 6;             // pixel group 0..3
    const int tl  = t & 63;             // owned a-column within quarter
    const int w32 = t & 31;             // staging lane (w)
    const int rg  = t >> 5;             // staging row group 0..7
    const int q   = blockIdx.x;         // a-quarter 0..3
    const int hb  = blockIdx.y;         // 0..7
    const int n   = blockIdx.z;
    const int aBase = q * ACOLS;

    // zero accumulators + preload sort metadata for the 16 rows
    #pragma unroll
    for (int i = t; i < 4 * CP1 * ACOLS; i += 256) { accS[i] = 0.f; accQ[i] = 0.f; }
    {
        const int swbase = (n * HH + hb * RPB) * 128;
        #pragma unroll
        for (int i = t; i < RPB * 128; i += 256) swsm[i] = gSW[swbase + i];
        const int sgbase = (n * HH + hb * RPB) * 4 * SEGW;
        #pragma unroll
        for (int i = t; i < RPB * 4 * SEGW; i += 256) segsm[i] = gSegs[sgbase + i];
    }

    const float* fbase = features + ((size_t)(n * AA + aBase)) * (HH * WW)
                       + (size_t)(hb * RPB) * WW;

    // prologue: load row 0 into registers (8 a-rows x 4 w-chunks per thread)
    float pf[32];
    #pragma unroll
    for (int k = 0; k < 8; k++)
        #pragma unroll
        for (int m = 0; m < 4; m++)
            pf[k * 4 + m] = fbase[(size_t)(rg + 8 * k) * (HH * WW) + w32 + 32 * m];

    __syncthreads();   // metadata + acc zero visible

    #pragma unroll 1
    for (int ch = 0; ch < RPB; ch++) {
        float* bufc = buf + (ch & 1) * (ACOLS * 129);

        // store current row tile to its stage (conflict-free stride 129)
        #pragma unroll
        for (int k = 0; k < 8; k++)
            #pragma unroll
            for (int m = 0; m < 4; m++)
                bufc[(rg + 8 * k) * 129 + w32 + 32 * m] = pf[k * 4 + m];

        // issue next row's loads now; consumed at iteration ch+1's STS
        if (ch + 1 < RPB) {
            #pragma unroll
            for (int k = 0; k < 8; k++)
                #pragma unroll
                for (int m = 0; m < 4; m++)
                    pf[k * 4 + m] = fbase[(size_t)(rg + 8 * k) * (HH * WW)
                                          + (ch + 1) * WW + w32 + 32 * m];
        }
        __syncthreads();   // stage filled; orders accum(ch-1) vs STS(ch+1)

        // segment-loop accumulation: group g -> sorted pixels [32g, 32g+32)
        {
            const unsigned char*  swr = swsm + ch * 128 + g * 32;
            const unsigned short* sgr = segsm + (ch * 4 + g) * SEGW;
            const int nseg = sgr[0];
            int idx = 0;
            float* aS = accS + g * CP1 * ACOLS + tl;
            float* aQ = accQ + g * CP1 * ACOLS + tl;
            #pragma unroll 1
            for (int si = 1; si <= nseg; si++) {
                int sc  = sgr[si];                 // uniform LDS
                int cnt = sc & 255;
                int cls = sc >> 8;
                float s = 0.f, qq = 0.f;
                #pragma unroll 1
                for (int j = 0; j < cnt; j++) {    // uniform trip count
                    float f = bufc[tl * 129 + swr[idx + j]];
                    s  += f;
                    qq += f * f;
                }
                idx += cnt;
                aS[cls * ACOLS] += s;              // unconditional flush
                aQ[cls * ACOLS] += qq;
            }
        }
    }
    __syncthreads();

    // merge 4 groups, single coalesced atomic flush
    #pragma unroll
    for (int i = t; i < CP1 * ACOLS; i += 256) {
        int c = i >> 6, al = i & 63;
        float vs = 0.f, vq = 0.f;
        #pragma unroll
        for (int gg = 0; gg < 4; gg++) {
            vs += accS[(gg * CP1 + c) * ACOLS + al];
            vq += accQ[(gg * CP1 + c) * ACOLS + al];
        }
        atomicAdd(&gSums[c * AA + aBase + al], vs);
        atomicAdd(&gSq[c * AA + aBase + al],   vq);
    }
}

// ---------------------------------------------------------------------------
// K2: grid = 19 blocks (one per class l; ncov row 19 never read: lab0<=18).
// fc staged in smem; c-loop fully unrolled -> 19 independent shuffle chains.
// ---------------------------------------------------------------------------
__global__ __launch_bounds__(256)
void cov_s_kernel(const float* __restrict__ fc,
                  const float* __restrict__ Ave,
                  const float* __restrict__ CoV,
                  const float* __restrict__ Amount,
                  const int* __restrict__ ratio_p) {
    __shared__ float Wsm[CC * AA];
    __shared__ float red[CC][8];
    const int l = blockIdx.x;          // 0..18
    const int t = threadIdx.x;         // 0..255 == feature index a
    const int lane = t & 31, wid = t >> 5;

    #pragma unroll
    for (int c = 0; c < CC; c++) Wsm[c * AA + t] = fc[c * AA + t];

    float cntv = gCount[l];
    float sums = gSums[l * AA + t];
    float sq   = gSq[l * AA + t];
    float avev = Ave[l * AA + t];
    float covv = CoV[l * AA + t];
    float amov = Amount[l];
    float r    = (float)(*ratio_p);    // low 4 LE bytes: correct for i32 & i64

    float cntc = (cntv == 0.f) ? 1.f : cntv;
    float ave  = sums / cntc;
    float var  = sq / cntc - ave * ave;
    float denom = cntv + amov;
    float wcv  = (denom > 0.f) ? (cntv / denom) : 0.f;
    float dd   = avev - ave;
    float ncov = covv * (1.f - wcv) + var * wcv + wcv * (1.f - wcv) * dd * dd;

    __syncthreads();
    float wl = Wsm[l * AA + t];

    #pragma unroll
    for (int c = 0; c < CC; c++) {
        float d = Wsm[c * AA + t] - wl;
        float v = ncov * d * d;
        #pragma unroll
        for (int o = 16; o; o >>= 1) v += __shfl_down_sync(0xffffffffu, v, o);
        if (lane == 0) red[c][wid] = v;
    }
    __syncthreads();
    if (t < CC) {
        float s = 0.f;
        #pragma unroll
        for (int k = 0; k < 8; k++) s += red[t][k];
        gS[l * CC + t] = r * s;
    }
}

// ---------------------------------------------------------------------------
// K3: out[n,c,h,w] = y[n,c,h,w] + 0.5 * S[l(n,h,w), c] * (l != 255)
// 4 blocks per (n,c) -> 608 blocks, 256 threads, float4/uchar4
// ---------------------------------------------------------------------------
__global__ __launch_bounds__(256, 4)
void aug_kernel(const float* __restrict__ y, float* __restrict__ out) {
    __shared__ float Ssm[CP1];
    const int t = threadIdx.x;                 // 0..255
    const int bq = blockIdx.x & 3;             // h-quarter
    const int nc = blockIdx.x >> 2;
    const int n = nc / CC;
    const int c = nc % CC;

    if (t < CP1) Ssm[t] = (t < CC) ? (0.5f * gS[t * CC + c]) : 0.f;
    __syncthreads();

    const size_t plane = ((size_t)n * CC + c) * (HH * WW);
    const int qoff = bq * (HH * WW / 16);      // in float4 units
    const float4* y4 = (const float4*)(y + plane) + qoff;
    float4*       o4 = (float4*)(out + plane) + qoff;
    const uchar4* l4 = (const uchar4*)(gLab + (size_t)n * (HH * WW)) + qoff;

    #pragma unroll 4
    for (int i = t; i < (HH * WW) / 16; i += 256) {
        uchar4 lb = l4[i];
        float4 v  = y4[i];
        if (lb.x != 255) v.x += Ssm[lb.x];
        if (lb.y != 255) v.y += Ssm[lb.y];
        if (lb.z != 255) v.z += Ssm[lb.z];
        if (lb.w != 255) v.w += Ssm[lb.w];
        o4[i] = v;
    }
}

// ---------------------------------------------------------------------------
extern "C" void kernel_launch(void* const* d_in, const int* in_sizes, int n_in,
                              void* d_out, int out_size) {
    const float* features = (const float*)d_in[0];
    const float* y        = (const float*)d_in[1];
    const float* fc       = (const float*)d_in[2];
    const float* Ave      = (const float*)d_in[3];
    const float* CoV      = (const float*)d_in[4];
    const float* Amount   = (const float*)d_in[5];
    const int*   target_w = (const int*)d_in[6];   // int32 or int64 (probed)
    const int*   ratio    = (const int*)d_in[7];
    float*       out      = (float*)d_out;

    // launch idx 0: dtype probe
    detect_kernel<<<1, 256>>>(target_w);
    // launch idx 1: zero accumulators
    zero_kernel<<<(CP1 * AA + 255) / 256, 256>>>();
    // launch idx 2: per-row label sort + segment extraction
    sort_kernel<<<NN * HH, 128>>>(target_w);

    // launch idx 3 (the ncu-captured slot): stats
    const int smem1 = (2 * ACOLS * 129 + 8 * CP1 * ACOLS) * 4
                    + RPB * 4 * SEGW * 2 + RPB * 128;
    cudaFuncSetAttribute(stats_kernel, cudaFuncAttributeMaxDynamicSharedMemorySize, smem1);
    dim3 g1(4, HH / RPB, NN);
    stats_kernel<<<g1, 256, smem1>>>(features);

    // launch idx 4: covariance update + S table
    cov_s_kernel<<<CC, 256>>>(fc, Ave, CoV, Amount, ratio);

    // launch idx 5: output
    aug_kernel<<<NN * CC * 4, 256>>>(y, out);
}

// round 10
// speedup vs baseline: 1.0899x; 1.0829x over previous
#include <cuda_runtime.h>
#include <cuda_bf16.h>
#include <cstdint>

// Problem constants
#define NN 8
#define AA 256
#define HH 128
#define WW 128
#define CC 19
#define CP1 20
#define HT 1024
#define WT 1024
#define RPB 16             // h-rows per stats block
#define ACOLS 64           // a-columns per stats block
#define SEGW 22            // ushorts per window segment record (1 cnt + <=20 segs + pad)

// Device scratch (no cudaMalloc allowed)
__device__ float gSums[CP1 * AA];
__device__ float gSq[CP1 * AA];
__device__ float gCount[32];
__device__ float gS[CP1 * CC];
__device__ unsigned char gLab[NN * HH * WW];
__device__ unsigned char gPos[NN * HH * WW];         // per-row sorted position of pixel w
__device__ unsigned short gSegs[NN * HH * 4 * SEGW]; // per-row per-32-window segments
__device__ int gIs64;

// ---------------------------------------------------------------------------
// K0a: detect target dtype (int32 vs int64). int64 labels in [0,19): every
// odd 32-bit word is a zero high-word. Reads first 8192 words only (safe).
// ---------------------------------------------------------------------------
__global__ void detect_kernel(const int* __restrict__ tw) {
    __shared__ int anynz;
    if (threadIdx.x == 0) anynz = 0;
    __syncthreads();
    int v = 0;
    #pragma unroll
    for (int k = 0; k < 16; k++) {
        int idx = threadIdx.x * 16 + k;          // 0..4095
        v |= tw[idx * 2 + 1];                    // word idx <= 8191
    }
    if (v != 0) atomicOr(&anynz, 1);
    __syncthreads();
    if (threadIdx.x == 0) gIs64 = (anynz == 0) ? 1 : 0;
}

// ---------------------------------------------------------------------------
// K0b: zero the per-class accumulators
// ---------------------------------------------------------------------------
__global__ void zero_kernel() {
    int i = blockIdx.x * 256 + threadIdx.x;
    if (i < CP1 * AA) { gSums[i] = 0.f; gSq[i] = 0.f; }
    if (i < 32) gCount[i] = 0.f;
}

// ---------------------------------------------------------------------------
// K0c: per-row label fetch + counting sort + per-window segment extraction.
// One block per (n,h) row. Writes gPos (sorted position of each pixel w ->
// used to SCATTER features into sorted order during staging), gSegs
// (per-32-position-window (class<<8|count) descriptors over the sorted order),
// gLab (raw bytes), gCount.
// ---------------------------------------------------------------------------
__global__ void sort_kernel(const int* __restrict__ tw) {
    __shared__ int cnt[CP1];
    __shared__ int offs[CP1];
    __shared__ unsigned char slab[128];
    const int t = threadIdx.x;          // 0..127 (w)
    const int row = blockIdx.x;         // n*HH + h
    const int n = row >> 7;
    const int h = row & 127;

    long long eidx = ((long long)n * HT + (long long)h * 8) * WT + (long long)t * 8;
    int raw = gIs64 ? tw[eidx * 2] : tw[eidx];
    int l0 = (raw == 255) ? 0 : raw;
    if (l0 < 0) l0 = 0;
    if (l0 > CP1 - 1) l0 = CP1 - 1;

    if (t < CP1) cnt[t] = 0;
    __syncthreads();
    atomicAdd(&cnt[l0], 1);
    gLab[(size_t)row * WW + t] = (unsigned char)(raw & 0xFF);
    __syncthreads();
    if (t == 0) {
        int run = 0;
        #pragma unroll
        for (int c = 0; c < CP1; c++) { offs[c] = run; run += cnt[c]; }
    }
    if (t < CP1) atomicAdd(&gCount[t], (float)cnt[t]);
    __syncthreads();
    int pos = atomicAdd(&offs[l0], 1);
    slab[pos] = (unsigned char)l0;
    gPos[(size_t)row * WW + t] = (unsigned char)pos;
    __syncthreads();

    // per-32-window segment extraction (threads 0..3, serial scan of 32)
    if (t < 4) {
        unsigned short* out = gSegs + ((size_t)row * 4 + t) * SEGW;
        int base = t * 32;
        int run = slab[base];
        int c0 = 1, ns = 0;
        #pragma unroll 1
        for (int i = 1; i < 32; i++) {
            int c = slab[base + i];
            if (c == run) { c0++; }
            else {
                out[1 + ns] = (unsigned short)((run << 8) | c0);
                ns++; run = c; c0 = 1;
            }
        }
        out[1 + ns] = (unsigned short)((run << 8) | c0);
        ns++;
        out[0] = (unsigned short)ns;
    }
}

// ---------------------------------------------------------------------------
// K1: stats. Block = (a-quarter of 64, h-block of 16 rows, n) -> 256 blocks.
// 256 threads, ~110KB dynamic smem -> 2 CTA/SM.
// PERMUTED STAGING: features are scattered into buf at their SORTED position
// (pos[w]) instead of natural w. The accumulation loop then reads buf with
// SEQUENTIAL addresses: no per-pixel index load, no dependent LDS chain --
// independent LDS pipeline at the crossbar floor. (R8's gather had
// LDS.U8 -> LDS.32 dependent 58-cyc chains per pixel = the measured 52us.)
// Double-buffered stages, pf[32] register prefetch of the next row issued
// before the sync. Segment descriptors give uniform nested loops: one
// unconditional flush per segment. One coalesced atomic flush per block.
// ---------------------------------------------------------------------------
__global__ __launch_bounds__(256, 2)
void stats_kernel(const float* __restrict__ features) {
    extern __shared__ float sm[];
    float* buf  = sm;                              // [2][ACOLS*129]
    float* accS = sm + 2 * ACOLS * 129;            // [4][CP1][ACOLS]
    float* accQ = accS + 4 * CP1 * ACOLS;          // [4][CP1][ACOLS]
    unsigned short* segsm = (unsigned short*)(accQ + 4 * CP1 * ACOLS); // [RPB*4*SEGW]
    unsigned char*  possm = (unsigned char*)(segsm + RPB * 4 * SEGW);  // [RPB*128]

    const int t   = threadIdx.x;        // 0..255
    const int g   = t >> 6;             // pixel group 0..3
    const int tl  = t & 63;             // owned a-column within quarter
    const int w32 = t & 31;             // staging lane (w)
    const int rg  = t >> 5;             // staging row group 0..7
    const int q   = blockIdx.x;         // a-quarter 0..3
    const int hb  = blockIdx.y;         // 0..7
    const int n   = blockIdx.z;
    const int aBase = q * ACOLS;

    // zero accumulators + preload sort metadata for the 16 rows
    #pragma unroll
    for (int i = t; i < 4 * CP1 * ACOLS; i += 256) { accS[i] = 0.f; accQ[i] = 0.f; }
    {
        const int pbase = (n * HH + hb * RPB) * 128;
        #pragma unroll
        for (int i = t; i < RPB * 128; i += 256) possm[i] = gPos[pbase + i];
        const int sgbase = (n * HH + hb * RPB) * 4 * SEGW;
        #pragma unroll
        for (int i = t; i < RPB * 4 * SEGW; i += 256) segsm[i] = gSegs[sgbase + i];
    }

    const float* fbase = features + ((size_t)(n * AA + aBase)) * (HH * WW)
                       + (size_t)(hb * RPB) * WW;

    // prologue: load row 0 into registers (8 a-rows x 4 w-chunks per thread)
    float pf[32];
    #pragma unroll
    for (int k = 0; k < 8; k++)
        #pragma unroll
        for (int m = 0; m < 4; m++)
            pf[k * 4 + m] = fbase[(size_t)(rg + 8 * k) * (HH * WW) + w32 + 32 * m];

    __syncthreads();   // metadata + acc zero visible

    #pragma unroll 1
    for (int ch = 0; ch < RPB; ch++) {
        float* bufc = buf + (ch & 1) * (ACOLS * 129);

        // sorted positions for this thread's 4 pixels (same for all 8 a-rows)
        int p0 = possm[ch * 128 + w32];
        int p1 = possm[ch * 128 + w32 + 32];
        int p2 = possm[ch * 128 + w32 + 64];
        int p3 = possm[ch * 128 + w32 + 96];

        // scatter current row tile into sorted order (stride 129)
        #pragma unroll
        for (int k = 0; k < 8; k++) {
            int rb = (rg + 8 * k) * 129;
            bufc[rb + p0] = pf[k * 4 + 0];
            bufc[rb + p1] = pf[k * 4 + 1];
            bufc[rb + p2] = pf[k * 4 + 2];
            bufc[rb + p3] = pf[k * 4 + 3];
        }

        // issue next row's loads now; consumed at iteration ch+1's STS
        if (ch + 1 < RPB) {
            #pragma unroll
            for (int k = 0; k < 8; k++)
                #pragma unroll
                for (int m = 0; m < 4; m++)
                    pf[k * 4 + m] = fbase[(size_t)(rg + 8 * k) * (HH * WW)
                                          + (ch + 1) * WW + w32 + 32 * m];
        }
        __syncthreads();   // stage filled; orders accum(ch-1) vs STS(ch+1)

        // segment-loop accumulation: group g -> sorted positions [32g, 32g+32)
        // sequential addresses: independent LDS, fully pipelined
        {
            const unsigned short* sgr = segsm + (ch * 4 + g) * SEGW;
            const int nseg = sgr[0];
            const float* bp = bufc + tl * 129 + g * 32;
            int idx = 0;
            float* aS = accS + g * CP1 * ACOLS + tl;
            float* aQ = accQ + g * CP1 * ACOLS + tl;
            #pragma unroll 1
            for (int si = 1; si <= nseg; si++) {
                int sc  = sgr[si];                 // uniform LDS
                int cnt = sc & 255;
                int cls = sc >> 8;
                float s = 0.f, qq = 0.f;
                #pragma unroll 4
                for (int j = 0; j < cnt; j++) {    // sequential, conflict-free
                    float f = bp[idx + j];
                    s  += f;
                    qq += f * f;
                }
                idx += cnt;
                aS[cls * ACOLS] += s;              // unconditional flush
                aQ[cls * ACOLS] += qq;
            }
        }
    }
    __syncthreads();

    // merge 4 groups, single coalesced atomic flush
    #pragma unroll
    for (int i = t; i < CP1 * ACOLS; i += 256) {
        int c = i >> 6, al = i & 63;
        float vs = 0.f, vq = 0.f;
        #pragma unroll
        for (int gg = 0; gg < 4; gg++) {
            vs += accS[(gg * CP1 + c) * ACOLS + al];
            vq += accQ[(gg * CP1 + c) * ACOLS + al];
        }
        atomicAdd(&gSums[c * AA + aBase + al], vs);
        atomicAdd(&gSq[c * AA + aBase + al],   vq);
    }
}

// ---------------------------------------------------------------------------
// K2: grid = 19 blocks (one per class l; ncov row 19 never read: lab0<=18).
// fc staged in smem; c-loop fully unrolled -> 19 independent shuffle chains.
// ---------------------------------------------------------------------------
__global__ __launch_bounds__(256)
void cov_s_kernel(const float* __restrict__ fc,
                  const float* __restrict__ Ave,
                  const float* __restrict__ CoV,
                  const float* __restrict__ Amount,
                  const int* __restrict__ ratio_p) {
    __shared__ float Wsm[CC * AA];
    __shared__ float red[CC][8];
    const int l = blockIdx.x;          // 0..18
    const int t = threadIdx.x;         // 0..255 == feature index a
    const int lane = t & 31, wid = t >> 5;

    #pragma unroll
    for (int c = 0; c < CC; c++) Wsm[c * AA + t] = fc[c * AA + t];

    float cntv = gCount[l];
    float sums = gSums[l * AA + t];
    float sq   = gSq[l * AA + t];
    float avev = Ave[l * AA + t];
    float covv = CoV[l * AA + t];
    float amov = Amount[l];
    float r    = (float)(*ratio_p);    // low 4 LE bytes: correct for i32 & i64

    float cntc = (cntv == 0.f) ? 1.f : cntv;
    float ave  = sums / cntc;
    float var  = sq / cntc - ave * ave;
    float denom = cntv + amov;
    float wcv  = (denom > 0.f) ? (cntv / denom) : 0.f;
    float dd   = avev - ave;
    float ncov = covv * (1.f - wcv) + var * wcv + wcv * (1.f - wcv) * dd * dd;

    __syncthreads();
    float wl = Wsm[l * AA + t];

    #pragma unroll
    for (int c = 0; c < CC; c++) {
        float d = Wsm[c * AA + t] - wl;
        float v = ncov * d * d;
        #pragma unroll
        for (int o = 16; o; o >>= 1) v += __shfl_down_sync(0xffffffffu, v, o);
        if (lane == 0) red[c][wid] = v;
    }
    __syncthreads();
    if (t < CC) {
        float s = 0.f;
        #pragma unroll
        for (int k = 0; k < 8; k++) s += red[t][k];
        gS[l * CC + t] = r * s;
    }
}

// ---------------------------------------------------------------------------
// K3: out[n,c,h,w] = y[n,c,h,w] + 0.5 * S[l(n,h,w), c] * (l != 255)
// 4 blocks per (n,c) -> 608 blocks, 256 threads, float4/uchar4
// ---------------------------------------------------------------------------
__global__ __launch_bounds__(256, 4)
void aug_kernel(const float* __restrict__ y, float* __restrict__ out) {
    __shared__ float Ssm[CP1];
    const int t = threadIdx.x;                 // 0..255
    const int bq = blockIdx.x & 3;             // h-quarter
    const int nc = blockIdx.x >> 2;
    const int n = nc / CC;
    const int c = nc % CC;

    if (t < CP1) Ssm[t] = (t < CC) ? (0.5f * gS[t * CC + c]) : 0.f;
    __syncthreads();

    const size_t plane = ((size_t)n * CC + c) * (HH * WW);
    const int qoff = bq * (HH * WW / 16);      // in float4 units
    const float4* y4 = (const float4*)(y + plane) + qoff;
    float4*       o4 = (float4*)(out + plane) + qoff;
    const uchar4* l4 = (const uchar4*)(gLab + (size_t)n * (HH * WW)) + qoff;

    #pragma unroll 4
    for (int i = t; i < (HH * WW) / 16; i += 256) {
        uchar4 lb = l4[i];
        float4 v  = y4[i];
        if (lb.x != 255) v.x += Ssm[lb.x];
        if (lb.y != 255) v.y += Ssm[lb.y];
        if (lb.z != 255) v.z += Ssm[lb.z];
        if (lb.w != 255) v.w += Ssm[lb.w];
        o4[i] = v;
    }
}

// ---------------------------------------------------------------------------
extern "C" void kernel_launch(void* const* d_in, const int* in_sizes, int n_in,
                              void* d_out, int out_size) {
    const float* features = (const float*)d_in[0];
    const float* y        = (const float*)d_in[1];
    const float* fc       = (const float*)d_in[2];
    const float* Ave      = (const float*)d_in[3];
    const float* CoV      = (const float*)d_in[4];
    const float* Amount   = (const float*)d_in[5];
    const int*   target_w = (const int*)d_in[6];   // int32 or int64 (probed)
    const int*   ratio    = (const int*)d_in[7];
    float*       out      = (float*)d_out;

    // launch idx 0: dtype probe
    detect_kernel<<<1, 256>>>(target_w);
    // launch idx 1: zero accumulators
    zero_kernel<<<(CP1 * AA + 255) / 256, 256>>>();
    // launch idx 2: per-row label sort + position/segment extraction
    sort_kernel<<<NN * HH, 128>>>(target_w);

    // launch idx 3 (the ncu-captured slot): stats
    const int smem1 = (2 * ACOLS * 129 + 8 * CP1 * ACOLS) * 4
                    + RPB * 4 * SEGW * 2 + RPB * 128;
    cudaFuncSetAttribute(stats_kernel, cudaFuncAttributeMaxDynamicSharedMemorySize, smem1);
    dim3 g1(4, HH / RPB, NN);
    stats_kernel<<<g1, 256, smem1>>>(features);

    // launch idx 4: covariance update + S table
    cov_s_kernel<<<CC, 256>>>(fc, Ave, CoV, Amount, ratio);

    // launch idx 5: output
    aug_kernel<<<NN * CC * 4, 256>>>(y, out);
}

// round 11
// speedup vs baseline: 1.1970x; 1.0983x over previous
#include <cuda_runtime.h>
#include <cuda_bf16.h>
#include <cstdint>

// Problem constants
#define NN 8
#define AA 256
#define HH 128
#define WW 128
#define CC 19
#define CP1 20
#define HT 1024
#define WT 1024
#define RPB 16             // h-rows per stats block
#define ACOLS 32           // a-columns per stats block
#define SEGW 22            // ushorts per window record: nseg + <=20 (cls<<8|start) + sentinel

// Device scratch (no cudaMalloc allowed)
__device__ float gSums[CP1 * AA];
__device__ float gSq[CP1 * AA];
__device__ float gCount[32];
__device__ float gS[CP1 * CC];
__device__ unsigned char gLab[NN * HH * WW];
__device__ unsigned char gPosT[NN * HH * WW];        // transposed: [row][w32][m] -> pos
__device__ unsigned short gSegs[NN * HH * 4 * SEGW]; // per-row per-32-window segments
__device__ int gIs64;

// ---------------------------------------------------------------------------
// K0a: detect target dtype (int32 vs int64). int64 labels in [0,19): every
// odd 32-bit word is a zero high-word. Reads first 8192 words only (safe).
// ---------------------------------------------------------------------------
__global__ void detect_kernel(const int* __restrict__ tw) {
    __shared__ int anynz;
    if (threadIdx.x == 0) anynz = 0;
    __syncthreads();
    int v = 0;
    #pragma unroll
    for (int k = 0; k < 16; k++) {
        int idx = threadIdx.x * 16 + k;          // 0..4095
        v |= tw[idx * 2 + 1];                    // word idx <= 8191
    }
    if (v != 0) atomicOr(&anynz, 1);
    __syncthreads();
    if (threadIdx.x == 0) gIs64 = (anynz == 0) ? 1 : 0;
}

// ---------------------------------------------------------------------------
// K0b: zero the per-class accumulators
// ---------------------------------------------------------------------------
__global__ void zero_kernel() {
    int i = blockIdx.x * 256 + threadIdx.x;
    if (i < CP1 * AA) { gSums[i] = 0.f; gSq[i] = 0.f; }
    if (i < 32) gCount[i] = 0.f;
}

// ---------------------------------------------------------------------------
// K0c: per-row label fetch + counting sort + per-window segment extraction.
// One block per (n,h) row. Writes gPosT (transposed sorted position of each
// pixel: [row][w&31][w>>5], so stats threads load uchar4), gSegs (per-32-
// position window: nseg, then (cls<<8|start) entries + sentinel start=32),
// gLab (raw bytes), gCount.
// ---------------------------------------------------------------------------
__global__ void sort_kernel(const int* __restrict__ tw) {
    __shared__ int cnt[CP1];
    __shared__ int offs[CP1];
    __shared__ unsigned char slab[128];
    const int t = threadIdx.x;          // 0..127 (w)
    const int row = blockIdx.x;         // n*HH + h
    const int n = row >> 7;
    const int h = row & 127;

    long long eidx = ((long long)n * HT + (long long)h * 8) * WT + (long long)t * 8;
    int raw = gIs64 ? tw[eidx * 2] : tw[eidx];
    int l0 = (raw == 255) ? 0 : raw;
    if (l0 < 0) l0 = 0;
    if (l0 > CP1 - 1) l0 = CP1 - 1;

    if (t < CP1) cnt[t] = 0;
    __syncthreads();
    atomicAdd(&cnt[l0], 1);
    gLab[(size_t)row * WW + t] = (unsigned char)(raw & 0xFF);
    __syncthreads();
    if (t == 0) {
        int run = 0;
        #pragma unroll
        for (int c = 0; c < CP1; c++) { offs[c] = run; run += cnt[c]; }
    }
    if (t < CP1) atomicAdd(&gCount[t], (float)cnt[t]);
    __syncthreads();
    int pos = atomicAdd(&offs[l0], 1);
    slab[pos] = (unsigned char)l0;
    gPosT[((size_t)row * 32 + (t & 31)) * 4 + (t >> 5)] = (unsigned char)pos;
    __syncthreads();

    // per-32-window segment extraction (threads 0..3, serial scan of 32)
    if (t < 4) {
        unsigned short* out = gSegs + ((size_t)row * 4 + t) * SEGW;
        int base = t * 32;
        int run = slab[base];
        out[1] = (unsigned short)(run << 8);     // start = 0
        int ns = 1;
        #pragma unroll 1
        for (int i = 1; i < 32; i++) {
            int c = slab[base + i];
            if (c != run) {
                out[1 + ns] = (unsigned short)((c << 8) | i);
                ns++; run = c;
            }
        }
        out[1 + ns] = 32;                        // sentinel: start = 32
        out[0] = (unsigned short)ns;
    }
}

// ---------------------------------------------------------------------------
// K1: stats. Block = (a-eighth of 32, h-block of 16 rows, n) -> 512 blocks.
// 256 threads, 56KB dynamic smem -> 4 CTA/SM (32 warps: 2x R10's latency
// hiding, the binding constraint at occ=21%).
// Permuted staging (features scattered to their sorted positions; positions
// come via one uchar4 LDG per thread per row from gPosT, prefetched with pf).
// Accum: window of 32 sorted positions handled by TWO warps split by segment
// PARITY (even/odd) -> class-disjoint, race-free shared bins, half the pixels
// per warp. Sequential LDS (no dependent chains). One atomic flush per block.
// ---------------------------------------------------------------------------
__global__ __launch_bounds__(256, 4)
void stats_kernel(const float* __restrict__ features) {
    extern __shared__ float sm[];
    float* buf  = sm;                              // [2][ACOLS*129]  33024 B
    float* accS = sm + 2 * ACOLS * 129;            // [4][CP1][32]    10240 B
    float* accQ = accS + 4 * CP1 * 32;             // [4][CP1][32]    10240 B
    unsigned short* segsm = (unsigned short*)(accQ + 4 * CP1 * 32); // 2816 B

    const int t   = threadIdx.x;        // 0..255
    const int g2  = t >> 6;             // window group 0..3
    const int par = (t >> 5) & 1;       // segment parity within group
    const int tl  = t & 31;             // owned a-column / lane
    const int w32 = t & 31;             // staging lane (w)
    const int wr  = t >> 5;             // staging warp 0..7
    const int q   = blockIdx.x;         // a-eighth 0..7
    const int hb  = blockIdx.y;         // 0..7
    const int n   = blockIdx.z;
    const int aBase = q * ACOLS;
    const int row0  = n * HH + hb * RPB;

    // zero accumulators + preload segment metadata for the 16 rows
    #pragma unroll
    for (int i = t; i < 4 * CP1 * 32; i += 256) { accS[i] = 0.f; accQ[i] = 0.f; }
    {
        const int sgbase = row0 * 4 * SEGW;
        #pragma unroll
        for (int i = t; i < RPB * 4 * SEGW; i += 256) segsm[i] = gSegs[sgbase + i];
    }

    const float* fbase = features + ((size_t)(n * AA + aBase)) * (HH * WW)
                       + (size_t)(hb * RPB) * WW;
    const unsigned char* ptbase = gPosT + ((size_t)row0 * 32 + w32) * 4;

    // prologue: positions + features of row 0 (warp wr stages a-rows wr+8k)
    uchar4 pv = *(const uchar4*)ptbase;
    float pf[16];
    #pragma unroll
    for (int k = 0; k < 4; k++)
        #pragma unroll
        for (int m = 0; m < 4; m++)
            pf[k * 4 + m] = fbase[(size_t)(wr + 8 * k) * (HH * WW) + w32 + 32 * m];

    __syncthreads();   // metadata + acc zero visible

    #pragma unroll 1
    for (int ch = 0; ch < RPB; ch++) {
        float* bufc = buf + (ch & 1) * (ACOLS * 129);

        // scatter current row tile into sorted order (stride 129)
        #pragma unroll
        for (int k = 0; k < 4; k++) {
            int rb = (wr + 8 * k) * 129;
            bufc[rb + pv.x] = pf[k * 4 + 0];
            bufc[rb + pv.y] = pf[k * 4 + 1];
            bufc[rb + pv.z] = pf[k * 4 + 2];
            bufc[rb + pv.w] = pf[k * 4 + 3];
        }

        // prefetch next row's positions + features (consumed at ch+1's STS)
        uchar4 pvn = pv;
        if (ch + 1 < RPB) {
            pvn = *(const uchar4*)(ptbase + (ch + 1) * (32 * 4));
            #pragma unroll
            for (int k = 0; k < 4; k++)
                #pragma unroll
                for (int m = 0; m < 4; m++)
                    pf[k * 4 + m] = fbase[(size_t)(wr + 8 * k) * (HH * WW)
                                          + (ch + 1) * WW + w32 + 32 * m];
        }
        __syncthreads();   // stage filled; orders accum(ch-1) vs STS(ch+1)

        // segment accumulation: group g2 -> window [32*g2, 32*g2+32);
        // this warp takes segments of its parity (class-disjoint vs peer warp)
        {
            const unsigned short* sgr = segsm + (ch * 4 + g2) * SEGW;
            const int nseg = sgr[0];
            const float* bp = bufc + tl * 129 + g2 * 32;
            float* aS = accS + g2 * CP1 * 32 + tl;
            float* aQ = accQ + g2 * CP1 * 32 + tl;
            #pragma unroll 1
            for (int si = 1 + par; si <= nseg; si += 2) {
                int e     = sgr[si];               // uniform LDS
                int cls   = e >> 8;
                int start = e & 255;
                int end   = sgr[si + 1] & 255;     // next start / sentinel 32
                float s = 0.f, qq = 0.f;
                #pragma unroll 2
                for (int j = start; j < end; j++) {  // sequential, conflict-free
                    float f = bp[j];
                    s  += f;
                    qq += f * f;
                }
                aS[cls * 32] += s;                 // race-free: parity-disjoint
                aQ[cls * 32] += qq;
            }
        }
        pv = pvn;
    }
    __syncthreads();

    // merge 4 groups, single coalesced atomic flush
    #pragma unroll
    for (int i = t; i < CP1 * 32; i += 256) {
        int c = i >> 5, al = i & 31;
        float vs = 0.f, vq = 0.f;
        #pragma unroll
        for (int gg = 0; gg < 4; gg++) {
            vs += accS[(gg * CP1 + c) * 32 + al];
            vq += accQ[(gg * CP1 + c) * 32 + al];
        }
        atomicAdd(&gSums[c * AA + aBase + al], vs);
        atomicAdd(&gSq[c * AA + aBase + al],   vq);
    }
}

// ---------------------------------------------------------------------------
// K2: grid = 19 blocks (one per class l; ncov row 19 never read: lab0<=18).
// fc staged in smem; c-loop fully unrolled -> 19 independent shuffle chains.
// ---------------------------------------------------------------------------
__global__ __launch_bounds__(256)
void cov_s_kernel(const float* __restrict__ fc,
                  const float* __restrict__ Ave,
                  const float* __restrict__ CoV,
                  const float* __restrict__ Amount,
                  const int* __restrict__ ratio_p) {
    __shared__ float Wsm[CC * AA];
    __shared__ float red[CC][8];
    const int l = blockIdx.x;          // 0..18
    const int t = threadIdx.x;         // 0..255 == feature index a
    const int lane = t & 31, wid = t >> 5;

    #pragma unroll
    for (int c = 0; c < CC; c++) Wsm[c * AA + t] = fc[c * AA + t];

    float cntv = gCount[l];
    float sums = gSums[l * AA + t];
    float sq   = gSq[l * AA + t];
    float avev = Ave[l * AA + t];
    float covv = CoV[l * AA + t];
    float amov = Amount[l];
    float r    = (float)(*ratio_p);    // low 4 LE bytes: correct for i32 & i64

    float cntc = (cntv == 0.f) ? 1.f : cntv;
    float ave  = sums / cntc;
    float var  = sq / cntc - ave * ave;
    float denom = cntv + amov;
    float wcv  = (denom > 0.f) ? (cntv / denom) : 0.f;
    float dd   = avev - ave;
    float ncov = covv * (1.f - wcv) + var * wcv + wcv * (1.f - wcv) * dd * dd;

    __syncthreads();
    float wl = Wsm[l * AA + t];

    #pragma unroll
    for (int c = 0; c < CC; c++) {
        float d = Wsm[c * AA + t] - wl;
        float v = ncov * d * d;
        #pragma unroll
        for (int o = 16; o; o >>= 1) v += __shfl_down_sync(0xffffffffu, v, o);
        if (lane == 0) red[c][wid] = v;
    }
    __syncthreads();
    if (t < CC) {
        float s = 0.f;
        #pragma unroll
        for (int k = 0; k < 8; k++) s += red[t][k];
        gS[l * CC + t] = r * s;
    }
}

// ---------------------------------------------------------------------------
// K3: out[n,c,h,w] = y[n,c,h,w] + 0.5 * S[l(n,h,w), c] * (l != 255)
// 4 blocks per (n,c) -> 608 blocks, 256 threads, float4/uchar4
// ---------------------------------------------------------------------------
__global__ __launch_bounds__(256, 4)
void aug_kernel(const float* __restrict__ y, float* __restrict__ out) {
    __shared__ float Ssm[CP1];
    const int t = threadIdx.x;                 // 0..255
    const int bq = blockIdx.x & 3;             // h-quarter
    const int nc = blockIdx.x >> 2;
    const int n = nc / CC;
    const int c = nc % CC;

    if (t < CP1) Ssm[t] = (t < CC) ? (0.5f * gS[t * CC + c]) : 0.f;
    __syncthreads();

    const size_t plane = ((size_t)n * CC + c) * (HH * WW);
    const int qoff = bq * (HH * WW / 16);      // in float4 units
    const float4* y4 = (const float4*)(y + plane) + qoff;
    float4*       o4 = (float4*)(out + plane) + qoff;
    const uchar4* l4 = (const uchar4*)(gLab + (size_t)n * (HH * WW)) + qoff;

    #pragma unroll 4
    for (int i = t; i < (HH * WW) / 16; i += 256) {
        uchar4 lb = l4[i];
        float4 v  = y4[i];
        if (lb.x != 255) v.x += Ssm[lb.x];
        if (lb.y != 255) v.y += Ssm[lb.y];
        if (lb.z != 255) v.z += Ssm[lb.z];
        if (lb.w != 255) v.w += Ssm[lb.w];
        o4[i] = v;
    }
}

// ---------------------------------------------------------------------------
extern "C" void kernel_launch(void* const* d_in, const int* in_sizes, int n_in,
                              void* d_out, int out_size) {
    const float* features = (const float*)d_in[0];
    const float* y        = (const float*)d_in[1];
    const float* fc       = (const float*)d_in[2];
    const float* Ave      = (const float*)d_in[3];
    const float* CoV      = (const float*)d_in[4];
    const float* Amount   = (const float*)d_in[5];
    const int*   target_w = (const int*)d_in[6];   // int32 or int64 (probed)
    const int*   ratio    = (const int*)d_in[7];
    float*       out      = (float*)d_out;

    // launch idx 0: dtype probe
    detect_kernel<<<1, 256>>>(target_w);
    // launch idx 1: zero accumulators
    zero_kernel<<<(CP1 * AA + 255) / 256, 256>>>();
    // launch idx 2: per-row label sort + position/segment extraction
    sort_kernel<<<NN * HH, 128>>>(target_w);

    // launch idx 3 (the ncu-captured slot): stats
    const int smem1 = (2 * ACOLS * 129 + 8 * CP1 * 32) * 4 + RPB * 4 * SEGW * 2;
    cudaFuncSetAttribute(stats_kernel, cudaFuncAttributeMaxDynamicSharedMemorySize, smem1);
    dim3 g1(8, HH / RPB, NN);
    stats_kernel<<<g1, 256, smem1>>>(features);

    // launch idx 4: covariance update + S table
    cov_s_kernel<<<CC, 256>>>(fc, Ave, CoV, Amount, ratio);

    // launch idx 5: output
    aug_kernel<<<NN * CC * 4, 256>>>(y, out);
}